// round 16
// baseline (speedup 1.0000x reference)
#include <cuda_runtime.h>
#include <cuda_fp16.h>
#include <math.h>
#include <stdint.h>

#define G 64      // B*T graphs
#define NN 1024   // nodes per graph
#define FF 64     // features
#define WP 72     // smem pitch (floats) for prep W tile
#define MP 36     // mask smem pitch (words), 144B
#define NCH 4     // pipeline chunks
#define NGC (G / NCH)   // graphs per chunk = 16

// Scratch (device globals: allocation-free rule)
__device__ __half   g_WhhT[G * FF * NN];    // 8 MB, [g][f][j] fp16 (plain)
__device__ float    g_s1[G * NN];
__device__ __half   g_yh[G * NN];           // e^{s2}/16
__device__ __half   g_zh[G * NN];           // e^{0.2 s2}/16
__device__ __half   g_s2h[G * NN];          // s2 (branch compare)
__device__ uint32_t g_mask[G * NN * 32];    // plain bitmasks: word w bit b = adj[r][32w+b]

__device__ __forceinline__ float f2tf32(float x) {
    float r;
    asm("cvt.rna.tf32.f32 %0, %1;" : "=f"(r) : "f"(x));
    return r;
}
__device__ __forceinline__ uint32_t smem_u32(const void* p) {
    uint32_t a;
    asm("{ .reg .u64 t; cvta.to.shared.u64 t, %1; cvt.u32.u64 %0, t; }"
        : "=r"(a) : "l"(p));
    return a;
}
__device__ __forceinline__ uint32_t packh2(float x) {
    __half h = __float2half_rn(x);
    uint32_t u = (uint32_t)__half_as_ushort(h);
    return u | (u << 16);
}
__device__ __forceinline__ uint32_t hgt2m(uint32_t a, uint32_t b) {
    uint32_t d;
    asm("set.gt.u32.f16x2 %0, %1, %2;" : "=r"(d) : "r"(a), "r"(b));
    return d;
}
__device__ __forceinline__ uint32_t hmul2u(uint32_t a, uint32_t b) {
    uint32_t d;
    asm("mul.rn.f16x2 %0, %1, %2;" : "=r"(d) : "r"(a), "r"(b));
    return d;
}
#define CP_ASYNC16(dst, src) \
    asm volatile("cp.async.cg.shared.global [%0], [%1], 16;" \
                 :: "r"(dst), "l"(src) : "memory")
#define CP_COMMIT() asm volatile("cp.async.commit_group;" ::: "memory")
#define CP_WAIT(n)  asm volatile("cp.async.wait_group %0;" :: "n"(n) : "memory")

#define MMA_TF32(acc, a0, a1, a2, a3, b0, b1) \
    asm volatile( \
        "mma.sync.aligned.m16n8k8.row.col.f32.tf32.tf32.f32 " \
        "{%0,%1,%2,%3}, {%4,%5,%6,%7}, {%8,%9}, {%0,%1,%2,%3};" \
        : "+f"((acc)[0]), "+f"((acc)[1]), "+f"((acc)[2]), "+f"((acc)[3]) \
        : "r"(a0), "r"(a1), "r"(a2), "r"(a3), "r"(b0), "r"(b1))

#define MMA_FP16(acc, a0, a1, a2, a3, b0, b1) \
    asm volatile( \
        "mma.sync.aligned.m16n8k16.row.col.f32.f16.f16.f32 " \
        "{%0,%1,%2,%3}, {%4,%5,%6,%7}, {%8,%9}, {%0,%1,%2,%3};" \
        : "+f"((acc)[0]), "+f"((acc)[1]), "+f"((acc)[2]), "+f"((acc)[3]) \
        : "r"(a0), "r"(a1), "r"(a2), "r"(a3), "r"(b0), "r"(b1))

// ---------------------------------------------------------------------------
// Kernel P (per 16-graph chunk): blocks [0, NGC*8): wh (128 rows each);
// blocks [NGC*8, NGC*24): pack-compress (64 rows each). 256 threads.
// ---------------------------------------------------------------------------
__global__ __launch_bounds__(256) void prep_kernel(const float* __restrict__ h,
                                                   const int* __restrict__ adj,
                                                   const float* __restrict__ W,
                                                   const float* __restrict__ a,
                                                   int g0) {
    __shared__ float Ws[64 * WP];
    __shared__ float sA[128];

    const int tid  = threadIdx.x;
    const int lane = tid & 31;
    const int w    = tid >> 5;

    if (blockIdx.x >= NGC * 8) {
        // ---- compress: 8 warps x 8 rows = 64 rows per CTA, pack-based
        const int c = blockIdx.x - NGC * 8;
        const int base = g0 * NN + c * 64 + w * 8;
        #pragma unroll 1
        for (int rr = 0; rr < 8; rr += 2) {
            const int row0 = base + rr;
            const int row1 = row0 + 1;
            const int4* p0 = (const int4*)(adj + (size_t)row0 * NN);
            const int4* p1 = (const int4*)(adj + (size_t)row1 * NN);
            uint32_t w0 = 0, w1 = 0;
            #pragma unroll
            for (int q = 0; q < 8; q++) {
                int4 v0 = p0[lane * 8 + q];
                int4 v1 = p1[lane * 8 + q];
                uint32_t n0 = (uint32_t)(v0.x | (v0.y << 1) | (v0.z << 2) | (v0.w << 3));
                uint32_t n1 = (uint32_t)(v1.x | (v1.y << 1) | (v1.z << 2) | (v1.w << 3));
                w0 |= n0 << (4 * q);
                w1 |= n1 << (4 * q);
            }
            g_mask[(size_t)row0 * 32 + lane] = w0;
            g_mask[(size_t)row1 * 32 + lane] = w1;
        }
        return;
    }

    // ---- wh via tf32 mma: CTA covers 128 rows
    #pragma unroll
    for (int i = 0; i < 16; i++) {
        int idx = tid + i * 256;
        int k = idx >> 6, f = idx & 63;
        Ws[k * WP + f] = f2tf32(W[idx]);
    }
    if (tid < 128) sA[tid] = a[tid];
    __syncthreads();

    const int gq = lane >> 2;
    const int t  = lane & 3;
    const int r0 = g0 * NN + blockIdx.x * 128 + w * 16 + gq;
    const int r1 = r0 + 8;
    const float* h0 = h + (size_t)r0 * FF;
    const float* h1 = h + (size_t)r1 * FF;

    float acc[8][4];
    #pragma unroll
    for (int nt = 0; nt < 8; nt++)
        #pragma unroll
        for (int q = 0; q < 4; q++) acc[nt][q] = 0.f;

    #pragma unroll
    for (int ks = 0; ks < 8; ks++) {
        const int kb = ks * 8 + t;
        const uint32_t a0 = __float_as_uint(f2tf32(h0[kb]));
        const uint32_t a1 = __float_as_uint(f2tf32(h1[kb]));
        const uint32_t a2 = __float_as_uint(f2tf32(h0[kb + 4]));
        const uint32_t a3 = __float_as_uint(f2tf32(h1[kb + 4]));
        #pragma unroll
        for (int nt = 0; nt < 8; nt++) {
            const uint32_t b0 = __float_as_uint(Ws[kb * WP + nt * 8 + gq]);
            const uint32_t b1 = __float_as_uint(Ws[(kb + 4) * WP + nt * 8 + gq]);
            MMA_TF32(acc[nt], a0, a1, a2, a3, b0, b1);
        }
    }

    const int grk = r0 >> 10;
    const int pi0 = r0 & 1023;
    const int pi1 = r1 & 1023;
    __half* WT = g_WhhT + (size_t)grk * (FF * NN);

    float s1_0 = 0.f, s2_0 = 0.f, s1_1 = 0.f, s2_1 = 0.f;
    #pragma unroll
    for (int nt = 0; nt < 8; nt++) {
        const int c = nt * 8 + 2 * t;
        const float a1c0 = sA[c],      a1c1 = sA[c + 1];
        const float a2c0 = sA[64 + c], a2c1 = sA[64 + c + 1];
        s1_0 += acc[nt][0] * a1c0 + acc[nt][1] * a1c1;
        s2_0 += acc[nt][0] * a2c0 + acc[nt][1] * a2c1;
        s1_1 += acc[nt][2] * a1c0 + acc[nt][3] * a1c1;
        s2_1 += acc[nt][2] * a2c0 + acc[nt][3] * a2c1;
        WT[(c + 0) * NN + pi0] = __float2half_rn(acc[nt][0]);
        WT[(c + 1) * NN + pi0] = __float2half_rn(acc[nt][1]);
        WT[(c + 0) * NN + pi1] = __float2half_rn(acc[nt][2]);
        WT[(c + 1) * NN + pi1] = __float2half_rn(acc[nt][3]);
    }
    #pragma unroll
    for (int off = 1; off <= 2; off <<= 1) {
        s1_0 += __shfl_xor_sync(0xffffffffu, s1_0, off);
        s2_0 += __shfl_xor_sync(0xffffffffu, s2_0, off);
        s1_1 += __shfl_xor_sync(0xffffffffu, s1_1, off);
        s2_1 += __shfl_xor_sync(0xffffffffu, s2_1, off);
    }
    if (t == 0) {
        g_s1[r0] = s1_0;
        g_s1[r1] = s1_1;
        const int gb = grk * NN;
        g_s2h[gb + pi0] = __float2half_rn(s2_0);
        g_s2h[gb + pi1] = __float2half_rn(s2_1);
        g_yh[gb + pi0]  = __float2half_rn(__expf(s2_0) * 0.0625f);
        g_yh[gb + pi1]  = __float2half_rn(__expf(s2_1) * 0.0625f);
        g_zh[gb + pi0]  = __float2half_rn(__expf(0.2f * s2_0) * 0.0625f);
        g_zh[gb + pi1]  = __float2half_rn(__expf(0.2f * s2_1) * 0.0625f);
    }
}

// ---------------------------------------------------------------------------
// Kernel C (per 16-graph chunk): out[128,64] per CTA; R15 ATTN body verbatim.
// ---------------------------------------------------------------------------
#define AO_Y    0
#define AO_Z    2048
#define AO_S    4096
#define AO_LUT  6144
#define AO_MASK 6400
#define AO_W0   24832
#define AO_W1   29952
#define SMEM_DYN 35072

extern __shared__ char smc[];

__global__ __launch_bounds__(128, 4) void attn_mma(float* __restrict__ out, int g0) {
    const int tid  = threadIdx.x;
    const int lane = tid & 31;
    const int w    = tid >> 5;
    const int gq   = lane >> 2;
    const int t    = lane & 3;
    const int gr   = g0 + (blockIdx.x >> 3);
    const int i0   = (blockIdx.x & 7) << 7;

    uint32_t* yh2s  = (uint32_t*)(smc + AO_Y);
    uint32_t* zh2s  = (uint32_t*)(smc + AO_Z);
    uint32_t* s2h2s = (uint32_t*)(smc + AO_S);
    uint32_t* lutS  = (uint32_t*)(smc + AO_LUT);
    uint32_t* maskS = (uint32_t*)(smc + AO_MASK);
    const uint32_t sb = smem_u32(smc);

    if (tid < 4)
        lutS[tid] = ((tid & 1) ? 0x0000FFFFu : 0u) | ((tid & 2) ? 0xFFFF0000u : 0u);

    const uint32_t whoff[2] = { sb + AO_W0, sb + AO_W1 };
    const char* WTg = (const char*)(g_WhhT + (size_t)gr * (FF * NN));

    // prologue staging
    {
        const char* ys = (const char*)(g_yh  + (size_t)gr * NN);
        const char* zs = (const char*)(g_zh  + (size_t)gr * NN);
        const char* ss = (const char*)(g_s2h + (size_t)gr * NN);
        CP_ASYNC16(sb + AO_Y + tid * 16, ys + tid * 16);
        CP_ASYNC16(sb + AO_Z + tid * 16, zs + tid * 16);
        CP_ASYNC16(sb + AO_S + tid * 16, ss + tid * 16);
        const char* ms = (const char*)(g_mask + ((size_t)gr * NN + i0) * 32);
        #pragma unroll
        for (int qq = 0; qq < 8; qq++) {
            int idx = tid + qq * 128;
            int rr = idx >> 3, s = idx & 7;
            CP_ASYNC16(sb + AO_MASK + (uint32_t)(rr * 144 + s * 16), ms + rr * 128 + s * 16);
        }
        #pragma unroll
        for (int qq = 0; qq < 2; qq++) {
            int idx = tid + qq * 128;
            int f = idx >> 2, sg = idx & 3;
            CP_ASYNC16(whoff[0] + (uint32_t)(f * 80 + sg * 16),
                       WTg + f * 2048 + sg * 16);
        }
        CP_COMMIT();
    }

    const int ra = w * 32 + gq;
    const int rb = ra + 8, rc = ra + 16, rd = ra + 24;
    const float* s1g = g_s1 + (size_t)gr * NN + i0;
    const float s1A = s1g[ra], s1B = s1g[rb], s1C = s1g[rc], s1D = s1g[rd];
    const uint32_t nA = packh2(-s1A), rhA = packh2(__expf(-0.8f * s1A));
    const uint32_t nB = packh2(-s1B), rhB = packh2(__expf(-0.8f * s1B));
    const uint32_t nC = packh2(-s1C), rhC = packh2(__expf(-0.8f * s1C));
    const uint32_t nD = packh2(-s1D), rhD = packh2(__expf(-0.8f * s1D));

    float accA[9][4], accB[9][4];
    #pragma unroll
    for (int nt = 0; nt < 9; nt++)
        #pragma unroll
        for (int qq = 0; qq < 4; qq++) { accA[nt][qq] = 0.f; accB[nt][qq] = 0.f; }
    const uint32_t bz = (gq == 0) ? 0x3C003C00u : 0u;

    CP_WAIT(0);
    __syncthreads();

    for (int jc = 0; jc < 32; jc++) {
        if (jc > 0) __syncthreads();
        if (jc < 31) {
            const uint32_t dstb = whoff[(jc + 1) & 1];
            const int joff = (jc + 1) * 64;
            #pragma unroll
            for (int qq = 0; qq < 2; qq++) {
                int idx = tid + qq * 128;
                int f = idx >> 2, sg = idx & 3;
                CP_ASYNC16(dstb + (uint32_t)(f * 80 + sg * 16),
                           WTg + f * 2048 + joff + sg * 16);
            }
            CP_COMMIT();
            CP_WAIT(1);
        } else {
            CP_WAIT(0);
        }
        __syncthreads();

        const uint32_t* wb = (const uint32_t*)(smc + ((jc & 1) ? AO_W1 : AO_W0));
        const uint32_t mA = maskS[ra * MP + jc] >> (2 * t);
        const uint32_t mB = maskS[rb * MP + jc] >> (2 * t);
        const uint32_t mC = maskS[rc * MP + jc] >> (2 * t);
        const uint32_t mD = maskS[rd * MP + jc] >> (2 * t);
        const int tb = jc * 16 + t;

        #pragma unroll
        for (int ks = 0; ks < 2; ks++) {
            const int u0 = tb + ks * 8;
            const uint32_t y0 = yh2s[u0],  y1 = yh2s[u0 + 4];
            const uint32_t z0 = zh2s[u0],  z1 = zh2s[u0 + 4];
            const uint32_t s0 = s2h2s[u0], s1p = s2h2s[u0 + 4];
            const int shA = ks * 16, shB = ks * 16 + 8;

            uint32_t cm0 = hgt2m(s0, nA), cm1 = hgt2m(s1p, nA);
            uint32_t zz0 = hmul2u(z0, rhA), zz1 = hmul2u(z1, rhA);
            uint32_t pA0 = ((y0 & cm0) | (zz0 & ~cm0)) & lutS[(mA >> shA) & 3];
            uint32_t pA1 = ((y1 & cm1) | (zz1 & ~cm1)) & lutS[(mA >> shB) & 3];
            cm0 = hgt2m(s0, nB); cm1 = hgt2m(s1p, nB);
            zz0 = hmul2u(z0, rhB); zz1 = hmul2u(z1, rhB);
            uint32_t pB0 = ((y0 & cm0) | (zz0 & ~cm0)) & lutS[(mB >> shA) & 3];
            uint32_t pB1 = ((y1 & cm1) | (zz1 & ~cm1)) & lutS[(mB >> shB) & 3];
            cm0 = hgt2m(s0, nC); cm1 = hgt2m(s1p, nC);
            zz0 = hmul2u(z0, rhC); zz1 = hmul2u(z1, rhC);
            uint32_t pC0 = ((y0 & cm0) | (zz0 & ~cm0)) & lutS[(mC >> shA) & 3];
            uint32_t pC1 = ((y1 & cm1) | (zz1 & ~cm1)) & lutS[(mC >> shB) & 3];
            cm0 = hgt2m(s0, nD); cm1 = hgt2m(s1p, nD);
            zz0 = hmul2u(z0, rhD); zz1 = hmul2u(z1, rhD);
            uint32_t pD0 = ((y0 & cm0) | (zz0 & ~cm0)) & lutS[(mD >> shA) & 3];
            uint32_t pD1 = ((y1 & cm1) | (zz1 & ~cm1)) & lutS[(mD >> shB) & 3];

            const int rbw = gq * 20 + ks * 8 + t;
            #pragma unroll
            for (int nt = 0; nt < 8; nt++) {
                const uint32_t b0 = wb[nt * 160 + rbw];
                const uint32_t b1 = wb[nt * 160 + rbw + 4];
                MMA_FP16(accA[nt], pA0, pB0, pA1, pB1, b0, b1);
                MMA_FP16(accB[nt], pC0, pD0, pC1, pD1, b0, b1);
            }
            MMA_FP16(accA[8], pA0, pB0, pA1, pB1, bz, bz);
            MMA_FP16(accB[8], pC0, pD0, pC1, pD1, bz, bz);
        }
    }

    const float Za = __shfl_sync(0xffffffffu, accA[8][0], lane & 28);
    const float Zb = __shfl_sync(0xffffffffu, accA[8][2], lane & 28);
    const float Zc = __shfl_sync(0xffffffffu, accB[8][0], lane & 28);
    const float Zd = __shfl_sync(0xffffffffu, accB[8][2], lane & 28);
    const float iva = 1.0f / Za, ivb = 1.0f / Zb;
    const float ivc = 1.0f / Zc, ivd = 1.0f / Zd;

    float* oa = out + ((size_t)gr * NN + i0 + ra) * FF + 2 * t;
    float* ob = out + ((size_t)gr * NN + i0 + rb) * FF + 2 * t;
    float* oc = out + ((size_t)gr * NN + i0 + rc) * FF + 2 * t;
    float* od = out + ((size_t)gr * NN + i0 + rd) * FF + 2 * t;
    #pragma unroll
    for (int nt = 0; nt < 8; nt++) {
        float e0 = accA[nt][0] * iva, e1 = accA[nt][1] * iva;
        float e2 = accA[nt][2] * ivb, e3 = accA[nt][3] * ivb;
        float e4 = accB[nt][0] * ivc, e5 = accB[nt][1] * ivc;
        float e6 = accB[nt][2] * ivd, e7 = accB[nt][3] * ivd;
        e0 = e0 > 0.f ? e0 : expm1f(e0);  e1 = e1 > 0.f ? e1 : expm1f(e1);
        e2 = e2 > 0.f ? e2 : expm1f(e2);  e3 = e3 > 0.f ? e3 : expm1f(e3);
        e4 = e4 > 0.f ? e4 : expm1f(e4);  e5 = e5 > 0.f ? e5 : expm1f(e5);
        e6 = e6 > 0.f ? e6 : expm1f(e6);  e7 = e7 > 0.f ? e7 : expm1f(e7);
        *(float2*)(oa + nt * 8) = make_float2(e0, e1);
        *(float2*)(ob + nt * 8) = make_float2(e2, e3);
        *(float2*)(oc + nt * 8) = make_float2(e4, e5);
        *(float2*)(od + nt * 8) = make_float2(e6, e7);
    }
}

// ---------------------------------------------------------------------------
// Host: 4-chunk software pipeline across two streams (graph fork/join).
//   s0 (capture stream): prep(0..3), each followed by an event record.
//   s1: attn(c) after event(c). Overlaps attn(c) with prep(c+1).
// ---------------------------------------------------------------------------
extern "C" void kernel_launch(void* const* d_in, const int* in_sizes, int n_in,
                              void* d_out, int out_size) {
    const float* h   = (const float*)d_in[0];
    const int*   adj = (const int*)d_in[1];
    const float* W   = (const float*)d_in[2];
    const float* a   = (const float*)d_in[3];
    float* out = (float*)d_out;

    cudaFuncSetAttribute(attn_mma, cudaFuncAttributeMaxDynamicSharedMemorySize,
                         SMEM_DYN);

    cudaStream_t s1;
    cudaStreamCreateWithFlags(&s1, cudaStreamNonBlocking);
    cudaEvent_t fork, join, ep[NCH];
    cudaEventCreateWithFlags(&fork, cudaEventDisableTiming);
    cudaEventCreateWithFlags(&join, cudaEventDisableTiming);
    for (int c = 0; c < NCH; c++)
        cudaEventCreateWithFlags(&ep[c], cudaEventDisableTiming);

    // fork: s1 joins the capture graph
    cudaEventRecord(fork, 0);
    cudaStreamWaitEvent(s1, fork, 0);

    for (int c = 0; c < NCH; c++) {
        prep_kernel<<<NGC * 24, 256, 0, 0>>>(h, adj, W, a, c * NGC);
        cudaEventRecord(ep[c], 0);
        cudaStreamWaitEvent(s1, ep[c], 0);
        attn_mma<<<NGC * 8, 128, SMEM_DYN, s1>>>(out, c * NGC);
    }

    // join: capture stream waits for s1's tail
    cudaEventRecord(join, s1);
    cudaStreamWaitEvent(0, join, 0);
    // streams/events intentionally not destroyed (capture holds references)
}

// round 17
// speedup vs baseline: 1.5078x; 1.5078x over previous
#include <cuda_runtime.h>
#include <cuda_fp16.h>
#include <math.h>
#include <stdint.h>

#define G 64      // B*T graphs
#define NN 1024   // nodes per graph
#define FF 64     // features
#define WP 72     // smem pitch (floats) for prep W tile
#define MP 36     // mask smem pitch (words), 144B

// Scratch (device globals: allocation-free rule)
__device__ __half   g_WhhT[G * FF * NN];    // 8 MB, [g][f][j] fp16 (plain)
__device__ float    g_s1[G * NN];
__device__ __half   g_yh[G * NN];           // e^{s2}/16
__device__ __half   g_zh[G * NN];           // e^{0.2 s2}/16
__device__ __half   g_s2h[G * NN];          // s2 (branch compare)
__device__ uint32_t g_mask[G * NN * 32];    // plain bitmasks: word w bit b = adj[r][32w+b]

__device__ __forceinline__ float f2tf32(float x) {
    float r;
    asm("cvt.rna.tf32.f32 %0, %1;" : "=f"(r) : "f"(x));
    return r;
}
__device__ __forceinline__ uint32_t smem_u32(const void* p) {
    uint32_t a;
    asm("{ .reg .u64 t; cvta.to.shared.u64 t, %1; cvt.u32.u64 %0, t; }"
        : "=r"(a) : "l"(p));
    return a;
}
__device__ __forceinline__ uint32_t packh2(float x) {
    __half h = __float2half_rn(x);
    uint32_t u = (uint32_t)__half_as_ushort(h);
    return u | (u << 16);
}
__device__ __forceinline__ uint32_t hgt2m(uint32_t a, uint32_t b) {
    uint32_t d;
    asm("set.gt.u32.f16x2 %0, %1, %2;" : "=r"(d) : "r"(a), "r"(b));
    return d;
}
__device__ __forceinline__ uint32_t hmul2u(uint32_t a, uint32_t b) {
    uint32_t d;
    asm("mul.rn.f16x2 %0, %1, %2;" : "=r"(d) : "r"(a), "r"(b));
    return d;
}
#define CP_ASYNC16(dst, src) \
    asm volatile("cp.async.cg.shared.global [%0], [%1], 16;" \
                 :: "r"(dst), "l"(src) : "memory")
#define CP_COMMIT() asm volatile("cp.async.commit_group;" ::: "memory")
#define CP_WAIT(n)  asm volatile("cp.async.wait_group %0;" :: "n"(n) : "memory")

#define MMA_TF32(acc, a0, a1, a2, a3, b0, b1) \
    asm volatile( \
        "mma.sync.aligned.m16n8k8.row.col.f32.tf32.tf32.f32 " \
        "{%0,%1,%2,%3}, {%4,%5,%6,%7}, {%8,%9}, {%0,%1,%2,%3};" \
        : "+f"((acc)[0]), "+f"((acc)[1]), "+f"((acc)[2]), "+f"((acc)[3]) \
        : "r"(a0), "r"(a1), "r"(a2), "r"(a3), "r"(b0), "r"(b1))

#define MMA_FP16(acc, a0, a1, a2, a3, b0, b1) \
    asm volatile( \
        "mma.sync.aligned.m16n8k16.row.col.f32.f16.f16.f32 " \
        "{%0,%1,%2,%3}, {%4,%5,%6,%7}, {%8,%9}, {%0,%1,%2,%3};" \
        : "+f"((acc)[0]), "+f"((acc)[1]), "+f"((acc)[2]), "+f"((acc)[3]) \
        : "r"(a0), "r"(a1), "r"(a2), "r"(a3), "r"(b0), "r"(b1))

// ---------------------------------------------------------------------------
// Kernel P: blocks [0,512): wh via tf32 mma (128 rows/CTA);
//           blocks [512,1536): pack-compress (64 rows/CTA, no ballots).
// ---------------------------------------------------------------------------
__global__ __launch_bounds__(256) void prep_kernel(const float* __restrict__ h,
                                                   const int* __restrict__ adj,
                                                   const float* __restrict__ W,
                                                   const float* __restrict__ a) {
    __shared__ float Ws[64 * WP];
    __shared__ float sA[128];

    const int tid  = threadIdx.x;
    const int lane = tid & 31;
    const int w    = tid >> 5;

    if (blockIdx.x >= 512) {
        // ---- compress: 8 warps x 8 rows; lane packs word `lane` of each row
        const int base = (blockIdx.x - 512) * 64 + w * 8;
        #pragma unroll 1
        for (int rr = 0; rr < 8; rr += 2) {
            const int row0 = base + rr;
            const int row1 = row0 + 1;
            const int4* p0 = (const int4*)(adj + (size_t)row0 * NN);
            const int4* p1 = (const int4*)(adj + (size_t)row1 * NN);
            uint32_t w0 = 0, w1 = 0;
            #pragma unroll
            for (int q = 0; q < 8; q++) {
                int4 v0 = p0[lane * 8 + q];
                int4 v1 = p1[lane * 8 + q];
                uint32_t n0 = (uint32_t)(v0.x | (v0.y << 1) | (v0.z << 2) | (v0.w << 3));
                uint32_t n1 = (uint32_t)(v1.x | (v1.y << 1) | (v1.z << 2) | (v1.w << 3));
                w0 |= n0 << (4 * q);
                w1 |= n1 << (4 * q);
            }
            g_mask[(size_t)row0 * 32 + lane] = w0;
            g_mask[(size_t)row1 * 32 + lane] = w1;
        }
        return;
    }

    // ---- wh via tf32 mma: CTA covers 128 rows
    #pragma unroll
    for (int i = 0; i < 16; i++) {
        int idx = tid + i * 256;
        int k = idx >> 6, f = idx & 63;
        Ws[k * WP + f] = f2tf32(W[idx]);
    }
    if (tid < 128) sA[tid] = a[tid];
    __syncthreads();

    const int gq = lane >> 2;
    const int t  = lane & 3;
    const int r0 = blockIdx.x * 128 + w * 16 + gq;
    const int r1 = r0 + 8;
    const float* h0 = h + (size_t)r0 * FF;
    const float* h1 = h + (size_t)r1 * FF;

    float acc[8][4];
    #pragma unroll
    for (int nt = 0; nt < 8; nt++)
        #pragma unroll
        for (int q = 0; q < 4; q++) acc[nt][q] = 0.f;

    #pragma unroll
    for (int ks = 0; ks < 8; ks++) {
        const int kb = ks * 8 + t;
        const uint32_t a0 = __float_as_uint(f2tf32(h0[kb]));
        const uint32_t a1 = __float_as_uint(f2tf32(h1[kb]));
        const uint32_t a2 = __float_as_uint(f2tf32(h0[kb + 4]));
        const uint32_t a3 = __float_as_uint(f2tf32(h1[kb + 4]));
        #pragma unroll
        for (int nt = 0; nt < 8; nt++) {
            const uint32_t b0 = __float_as_uint(Ws[kb * WP + nt * 8 + gq]);
            const uint32_t b1 = __float_as_uint(Ws[(kb + 4) * WP + nt * 8 + gq]);
            MMA_TF32(acc[nt], a0, a1, a2, a3, b0, b1);
        }
    }

    const int grk = r0 >> 10;
    const int pi0 = r0 & 1023;
    const int pi1 = r1 & 1023;
    __half* WT = g_WhhT + (size_t)grk * (FF * NN);

    float s1_0 = 0.f, s2_0 = 0.f, s1_1 = 0.f, s2_1 = 0.f;
    #pragma unroll
    for (int nt = 0; nt < 8; nt++) {
        const int c = nt * 8 + 2 * t;
        const float a1c0 = sA[c],      a1c1 = sA[c + 1];
        const float a2c0 = sA[64 + c], a2c1 = sA[64 + c + 1];
        s1_0 += acc[nt][0] * a1c0 + acc[nt][1] * a1c1;
        s2_0 += acc[nt][0] * a2c0 + acc[nt][1] * a2c1;
        s1_1 += acc[nt][2] * a1c0 + acc[nt][3] * a1c1;
        s2_1 += acc[nt][2] * a2c0 + acc[nt][3] * a2c1;
        WT[(c + 0) * NN + pi0] = __float2half_rn(acc[nt][0]);
        WT[(c + 1) * NN + pi0] = __float2half_rn(acc[nt][1]);
        WT[(c + 0) * NN + pi1] = __float2half_rn(acc[nt][2]);
        WT[(c + 1) * NN + pi1] = __float2half_rn(acc[nt][3]);
    }
    #pragma unroll
    for (int off = 1; off <= 2; off <<= 1) {
        s1_0 += __shfl_xor_sync(0xffffffffu, s1_0, off);
        s2_0 += __shfl_xor_sync(0xffffffffu, s2_0, off);
        s1_1 += __shfl_xor_sync(0xffffffffu, s1_1, off);
        s2_1 += __shfl_xor_sync(0xffffffffu, s2_1, off);
    }
    if (t == 0) {
        g_s1[r0] = s1_0;
        g_s1[r1] = s1_1;
        const int gb = grk * NN;
        g_s2h[gb + pi0] = __float2half_rn(s2_0);
        g_s2h[gb + pi1] = __float2half_rn(s2_1);
        g_yh[gb + pi0]  = __float2half_rn(__expf(s2_0) * 0.0625f);
        g_yh[gb + pi1]  = __float2half_rn(__expf(s2_1) * 0.0625f);
        g_zh[gb + pi0]  = __float2half_rn(__expf(0.2f * s2_0) * 0.0625f);
        g_zh[gb + pi1]  = __float2half_rn(__expf(0.2f * s2_1) * 0.0625f);
    }
}

// ---------------------------------------------------------------------------
// Kernel C: out[128,64] per CTA, fp16 m16n8k16, plain masks, ones-column Z.
// 4-deep Wh buffer ring, prefetch distance 2, ONE syncthreads per chunk:
//   iter jc: commit c(jc+2) -> wait_group(2) (c(jc) complete) -> sync -> compute.
// Buffer reuse (jc+2)&3 == (jc-2)&3 is protected by the sync at iter jc-1.
// ---------------------------------------------------------------------------
#define AO_Y    0
#define AO_Z    2048
#define AO_S    4096
#define AO_LUT  6144
#define AO_MASK 6400
#define AO_WH   24832         // 4 buffers x 5120 B
#define WHB     5120
#define SMEM_DYN (AO_WH + 4 * WHB)   // 45312

extern __shared__ char smc[];

__global__ __launch_bounds__(128, 4) void attn_mma(float* __restrict__ out) {
    const int tid  = threadIdx.x;
    const int lane = tid & 31;
    const int w    = tid >> 5;
    const int gq   = lane >> 2;
    const int t    = lane & 3;
    const int gr   = blockIdx.x >> 3;
    const int i0   = (blockIdx.x & 7) << 7;

    uint32_t* yh2s  = (uint32_t*)(smc + AO_Y);
    uint32_t* zh2s  = (uint32_t*)(smc + AO_Z);
    uint32_t* s2h2s = (uint32_t*)(smc + AO_S);
    uint32_t* lutS  = (uint32_t*)(smc + AO_LUT);
    uint32_t* maskS = (uint32_t*)(smc + AO_MASK);
    const uint32_t sb = smem_u32(smc);

    if (tid < 4)
        lutS[tid] = ((tid & 1) ? 0x0000FFFFu : 0u) | ((tid & 2) ? 0xFFFF0000u : 0u);

    const char* WTg = (const char*)(g_WhhT + (size_t)gr * (FF * NN));
    const int fi = tid >> 2, sg = tid & 3;      // Wh staging: 128 thr cover 64f x 4seg

    // G0: y/z/s2 + masks + Wh chunk 0
    {
        const char* ys = (const char*)(g_yh  + (size_t)gr * NN);
        const char* zs = (const char*)(g_zh  + (size_t)gr * NN);
        const char* ss = (const char*)(g_s2h + (size_t)gr * NN);
        CP_ASYNC16(sb + AO_Y + tid * 16, ys + tid * 16);
        CP_ASYNC16(sb + AO_Z + tid * 16, zs + tid * 16);
        CP_ASYNC16(sb + AO_S + tid * 16, ss + tid * 16);
        const char* ms = (const char*)(g_mask + ((size_t)gr * NN + i0) * 32);
        #pragma unroll
        for (int qq = 0; qq < 8; qq++) {
            int idx = tid + qq * 128;
            int rr = idx >> 3, s = idx & 7;
            CP_ASYNC16(sb + AO_MASK + (uint32_t)(rr * 144 + s * 16), ms + rr * 128 + s * 16);
        }
        #pragma unroll
        for (int qq = 0; qq < 2; qq++) {
            int idx = tid + qq * 128;
            int f = idx >> 2, g4 = idx & 3;
            CP_ASYNC16(sb + AO_WH + (uint32_t)(f * 80 + g4 * 16),
                       WTg + f * 2048 + g4 * 16);
        }
        CP_COMMIT();
        // G1: Wh chunk 1
        #pragma unroll
        for (int qq = 0; qq < 2; qq++) {
            int idx = tid + qq * 128;
            int f = idx >> 2, g4 = idx & 3;
            CP_ASYNC16(sb + AO_WH + WHB + (uint32_t)(f * 80 + g4 * 16),
                       WTg + f * 2048 + 64 + g4 * 16);
        }
        CP_COMMIT();
    }

    const int ra = w * 32 + gq;
    const int rb = ra + 8, rc = ra + 16, rd = ra + 24;
    const float* s1g = g_s1 + (size_t)gr * NN + i0;
    const float s1A = s1g[ra], s1B = s1g[rb], s1C = s1g[rc], s1D = s1g[rd];
    const uint32_t nA = packh2(-s1A), rhA = packh2(__expf(-0.8f * s1A));
    const uint32_t nB = packh2(-s1B), rhB = packh2(__expf(-0.8f * s1B));
    const uint32_t nC = packh2(-s1C), rhC = packh2(__expf(-0.8f * s1C));
    const uint32_t nD = packh2(-s1D), rhD = packh2(__expf(-0.8f * s1D));

    float accA[9][4], accB[9][4];
    #pragma unroll
    for (int nt = 0; nt < 9; nt++)
        #pragma unroll
        for (int qq = 0; qq < 4; qq++) { accA[nt][qq] = 0.f; accB[nt][qq] = 0.f; }
    const uint32_t bz = (gq == 0) ? 0x3C003C00u : 0u;

    for (int jc = 0; jc < 32; jc++) {
        if (jc < 30) {      // stage chunk jc+2 into buffer (jc+2)&3
            const uint32_t dstb = sb + AO_WH + (uint32_t)(((jc + 2) & 3) * WHB);
            const int joff = (jc + 2) * 64;
            CP_ASYNC16(dstb + (uint32_t)(fi * 80 + sg * 16),
                       WTg + fi * 2048 + joff + sg * 16);
            CP_ASYNC16(dstb + (uint32_t)((fi + 32) * 80 + sg * 16),
                       WTg + (fi + 32) * 2048 + joff + sg * 16);
            CP_COMMIT();
            CP_WAIT(2);     // chunk jc's group complete
        } else {
            CP_WAIT(0);
        }
        __syncthreads();    // single barrier per chunk

        const uint32_t* wb = (const uint32_t*)(smc + AO_WH + (jc & 3) * WHB);
        const uint32_t mA = maskS[ra * MP + jc] >> (2 * t);
        const uint32_t mB = maskS[rb * MP + jc] >> (2 * t);
        const uint32_t mC = maskS[rc * MP + jc] >> (2 * t);
        const uint32_t mD = maskS[rd * MP + jc] >> (2 * t);
        const int tb = jc * 16 + t;

        #pragma unroll
        for (int ks = 0; ks < 2; ks++) {
            const int u0 = tb + ks * 8;
            const uint32_t y0 = yh2s[u0],  y1 = yh2s[u0 + 4];
            const uint32_t z0 = zh2s[u0],  z1 = zh2s[u0 + 4];
            const uint32_t s0 = s2h2s[u0], s1p = s2h2s[u0 + 4];
            const int shA = ks * 16, shB = ks * 16 + 8;

            uint32_t cm0 = hgt2m(s0, nA), cm1 = hgt2m(s1p, nA);
            uint32_t zz0 = hmul2u(z0, rhA), zz1 = hmul2u(z1, rhA);
            uint32_t pA0 = ((y0 & cm0) | (zz0 & ~cm0)) & lutS[(mA >> shA) & 3];
            uint32_t pA1 = ((y1 & cm1) | (zz1 & ~cm1)) & lutS[(mA >> shB) & 3];
            cm0 = hgt2m(s0, nB); cm1 = hgt2m(s1p, nB);
            zz0 = hmul2u(z0, rhB); zz1 = hmul2u(z1, rhB);
            uint32_t pB0 = ((y0 & cm0) | (zz0 & ~cm0)) & lutS[(mB >> shA) & 3];
            uint32_t pB1 = ((y1 & cm1) | (zz1 & ~cm1)) & lutS[(mB >> shB) & 3];
            cm0 = hgt2m(s0, nC); cm1 = hgt2m(s1p, nC);
            zz0 = hmul2u(z0, rhC); zz1 = hmul2u(z1, rhC);
            uint32_t pC0 = ((y0 & cm0) | (zz0 & ~cm0)) & lutS[(mC >> shA) & 3];
            uint32_t pC1 = ((y1 & cm1) | (zz1 & ~cm1)) & lutS[(mC >> shB) & 3];
            cm0 = hgt2m(s0, nD); cm1 = hgt2m(s1p, nD);
            zz0 = hmul2u(z0, rhD); zz1 = hmul2u(z1, rhD);
            uint32_t pD0 = ((y0 & cm0) | (zz0 & ~cm0)) & lutS[(mD >> shA) & 3];
            uint32_t pD1 = ((y1 & cm1) | (zz1 & ~cm1)) & lutS[(mD >> shB) & 3];

            const int rbw = gq * 20 + ks * 8 + t;
            #pragma unroll
            for (int nt = 0; nt < 8; nt++) {
                const uint32_t b0 = wb[nt * 160 + rbw];
                const uint32_t b1 = wb[nt * 160 + rbw + 4];
                MMA_FP16(accA[nt], pA0, pB0, pA1, pB1, b0, b1);
                MMA_FP16(accB[nt], pC0, pD0, pC1, pD1, b0, b1);
            }
            MMA_FP16(accA[8], pA0, pB0, pA1, pB1, bz, bz);
            MMA_FP16(accB[8], pC0, pD0, pC1, pD1, bz, bz);
        }
    }

    const float Za = __shfl_sync(0xffffffffu, accA[8][0], lane & 28);
    const float Zb = __shfl_sync(0xffffffffu, accA[8][2], lane & 28);
    const float Zc = __shfl_sync(0xffffffffu, accB[8][0], lane & 28);
    const float Zd = __shfl_sync(0xffffffffu, accB[8][2], lane & 28);
    const float iva = 1.0f / Za, ivb = 1.0f / Zb;
    const float ivc = 1.0f / Zc, ivd = 1.0f / Zd;

    float* oa = out + ((size_t)gr * NN + i0 + ra) * FF + 2 * t;
    float* ob = out + ((size_t)gr * NN + i0 + rb) * FF + 2 * t;
    float* oc = out + ((size_t)gr * NN + i0 + rc) * FF + 2 * t;
    float* od = out + ((size_t)gr * NN + i0 + rd) * FF + 2 * t;
    #pragma unroll
    for (int nt = 0; nt < 8; nt++) {
        float e0 = accA[nt][0] * iva, e1 = accA[nt][1] * iva;
        float e2 = accA[nt][2] * ivb, e3 = accA[nt][3] * ivb;
        float e4 = accB[nt][0] * ivc, e5 = accB[nt][1] * ivc;
        float e6 = accB[nt][2] * ivd, e7 = accB[nt][3] * ivd;
        e0 = e0 > 0.f ? e0 : expm1f(e0);  e1 = e1 > 0.f ? e1 : expm1f(e1);
        e2 = e2 > 0.f ? e2 : expm1f(e2);  e3 = e3 > 0.f ? e3 : expm1f(e3);
        e4 = e4 > 0.f ? e4 : expm1f(e4);  e5 = e5 > 0.f ? e5 : expm1f(e5);
        e6 = e6 > 0.f ? e6 : expm1f(e6);  e7 = e7 > 0.f ? e7 : expm1f(e7);
        *(float2*)(oa + nt * 8) = make_float2(e0, e1);
        *(float2*)(ob + nt * 8) = make_float2(e2, e3);
        *(float2*)(oc + nt * 8) = make_float2(e4, e5);
        *(float2*)(od + nt * 8) = make_float2(e6, e7);
    }
}

// ---------------------------------------------------------------------------
extern "C" void kernel_launch(void* const* d_in, const int* in_sizes, int n_in,
                              void* d_out, int out_size) {
    const float* h   = (const float*)d_in[0];
    const int*   adj = (const int*)d_in[1];
    const float* W   = (const float*)d_in[2];
    const float* a   = (const float*)d_in[3];
    float* out = (float*)d_out;

    cudaFuncSetAttribute(attn_mma, cudaFuncAttributeMaxDynamicSharedMemorySize,
                         SMEM_DYN);

    prep_kernel<<<512 + 1024, 256>>>(h, adj, W, a);
    attn_mma<<<G * 8, 128, SMEM_DYN>>>(out);
}